// round 11
// baseline (speedup 1.0000x reference)
#include <cuda_runtime.h>

#define NN 512          // T = U = 512
#define NT 512          // one CTA per batch: 16 warps, 1 column/thread
#define NW 16
#define RING 128        // ring slots per warp boundary (producer lead <= ~33)
#define C_CONST 1.0f
#define GEPS 1e-9f
#define MAXB 64

__device__ float g_costs[MAXB];
__device__ int g_ctr = 0;

// ---- fence-free 8B tag|value handoffs (8B accesses are single-copy atomic) ----
__device__ __forceinline__ void sts_vol64(unsigned long long* p, unsigned long long v) {
    unsigned a = (unsigned)__cvta_generic_to_shared(p);
    asm volatile("st.volatile.shared.b64 [%0], %1;" :: "r"(a), "l"(v) : "memory");
}
__device__ __forceinline__ unsigned long long lds_vol64(unsigned long long* p) {
    unsigned a = (unsigned)__cvta_generic_to_shared(p);
    unsigned long long v;
    asm volatile("ld.volatile.shared.b64 %0, [%1];" : "=l"(v) : "r"(a) : "memory");
    return v;
}

// ln(1+x) for x in [0,1] on the FMA pipe (no MUFU):
// ln(1+x) = ln(3/2) + ln(1+s), s = (2x-1)/3, |s| <= 1/3; 7-term series, |err| <= 2e-5
__device__ __forceinline__ float log1p_unit(float x) {
    float s = fmaf(x, 0.66666667f, -0.33333333f);
    float p = 0.14285714f;                 // 1/7
    p = fmaf(p, s, -0.16666667f);          // -1/6
    p = fmaf(p, s,  0.2f);                 //  1/5
    p = fmaf(p, s, -0.25f);                // -1/4
    p = fmaf(p, s,  0.33333333f);          //  1/3
    p = fmaf(p, s, -0.5f);                 // -1/2
    p = fmaf(p, s,  1.0f);                 //  1
    return fmaf(s, p, 0.40546511f);        // ln(3/2) + s*P(s)
}

__device__ __forceinline__ float transf(float a, float b, float A, float B) {
    float u = a * b;
    float w = 0.5f * (1.0f + u * rsqrtf(fmaf(u, u, GEPS)));   // 1 - gate
    float mn = fminf(A, B);
    float mx = fmaxf(A, B);
    float sm = mn - log1p_unit(__expf(mn - mx));              // softmin2 (poly log)
    return fmaf(w, sm, C_CONST);
}

// softmin3, min-arm exp folded to 1; INF-safe for boundary arms (MUFU log: on chain)
__device__ __forceinline__ float softmin3f(float a, float b, float c) {
    float mn    = fminf(a, fminf(b, c));
    float mx    = fmaxf(a, fmaxf(b, c));
    float ab_mn = fminf(a, b);
    float ab_mx = fmaxf(a, b);
    float md    = fmaxf(ab_mn, fminf(ab_mx, c));              // median
    float s = 1.0f + __expf(mn - md) + __expf(mn - mx);
    return mn - __logf(s);
}

__global__ __launch_bounds__(NT, 1)
void soft_msm_kernel(const float* __restrict__ x, const float* __restrict__ y,
                     float* __restrict__ out, int B) {
    __shared__ float4 sq[NN];                          // (x_i, sau_i, sau_i^2, 0)
    __shared__ unsigned long long bnd[NW - 1][RING];   // boundary rings (tag<<32 | val)

    const int b    = blockIdx.x;           // one CTA per batch
    const int t    = threadIdx.x;
    const int w    = t >> 5;
    const int lane = t & 31;
    const int jme  = t;                    // my column
    const int j0   = 32 * w;               // lane0's column in this warp

    const float* xb = x + b * NN;
    const float* yb = y + b * NN;

    const float yj  = yb[jme];
    const float al  = (jme > 0) ? (yj - yb[jme - 1]) : 0.0f;
    const float al2 = al * al;

    sq[t].x = xb[t];
    for (int i = t; i < (NW - 1) * RING; i += NT)
        ((unsigned long long*)bnd)[i] = 0xFFFFFFFF00000000ull;
    __syncthreads();
    {
        float x1 = sq[t].x;
        float s1 = (t > 0) ? (x1 - sq[t - 1].x) : 0.0f;
        sq[t].y = s1;
        sq[t].z = s1 * s1;
    }
    __syncthreads();

    const float INF = __int_as_float(0x7f800000);
    const bool leftINF = (w == 0);         // no producer; col-0 boundary arm

    float curC  = 0.0f;
    float pdiag = 0.0f;
    if (t == 0) { float d0 = sq[0].x - yj; curC = d0 * d0; }   // C[0,0]

    // ================= HEAD: d in [dstart, j0+31], generic body =================
    {
        const int dstart = leftINF ? 1 : j0;
        for (int d = dstart; d <= j0 + 31; ++d) {
            float fl = __shfl_up_sync(0xffffffffu, curC, 1);
            if (lane == 0) {
                if (leftINF) fl = INF;
                else {
                    unsigned long long pk = lds_vol64(&bnd[w - 1][(d - 1) & (RING - 1)]);
                    while ((int)(pk >> 32) != d - 1)
                        pk = lds_vol64(&bnd[w - 1][(d - 1) & (RING - 1)]);
                    fl = __uint_as_float((unsigned)pk);
                }
            }
            const int  i = d - jme;
            const bool v = (i >= 0);
            float4 q = sq[i & 511];
            float bx = q.x - yj;
            float m  = bx * bx;
            float ut = transf(q.y, bx, q.z, m);
            float lt = transf(al, -bx, al2, m);
            float dd = pdiag + m;
            float du = curC  + ut;
            float cl = fl    + lt;
            if (jme == 0) { dd = INF; cl = INF; }
            if (i == 0)   { dd = INF; du = INF; }
            float c = softmin3f(dd, du, cl);
            if (v) {
                pdiag = fl; curC = c;
                if (lane == 31 && w < NW - 1)
                    sts_vol64(&bnd[w][d & (RING - 1)],
                              ((unsigned long long)(unsigned)d << 32) |
                              (unsigned long long)__float_as_uint(c));
            }
        }
    }

    // ============ STEADY: d in [j0+32, j0+511], lean body, all lanes valid ============
    {
        // preamble: fromLeft for d = j0+32 (needs slot j0+31)
        float fl = __shfl_up_sync(0xffffffffu, curC, 1);
        if (leftINF) {
            if (lane == 0) fl = INF;
        } else {
            unsigned long long pk = lds_vol64(&bnd[w - 1][(j0 + 31) & (RING - 1)]);
            while ((int)(pk >> 32) != j0 + 31)
                pk = lds_vol64(&bnd[w - 1][(j0 + 31) & (RING - 1)]);
            if (lane == 0) fl = __uint_as_float((unsigned)pk);
        }

        #pragma unroll 2
        for (int d = j0 + 32; d <= j0 + 511; ++d) {
            const int i = d - jme;                 // 1..511, always interior
            float4 q = sq[i];
            float bx = q.x - yj;
            float m  = bx * bx;
            float ut = transf(q.y, bx, q.z, m);
            float lt = transf(al, -bx, al2, m);
            float dd = pdiag + m;
            float du = curC  + ut;
            float cl = fl    + lt;
            float c  = softmin3f(dd, du, cl);      // INF arm (leftINF lane0) absorbed exactly
            pdiag = fl;
            curC  = c;

            if (lane == 31 && w < NW - 1)
                sts_vol64(&bnd[w][d & (RING - 1)],
                          ((unsigned long long)(unsigned)d << 32) |
                          (unsigned long long)__float_as_uint(c));

            // fromLeft for next iteration (poll-ahead, off the critical chain)
            fl = __shfl_up_sync(0xffffffffu, c, 1);
            if (d <= j0 + 510) {
                if (leftINF) {
                    if (lane == 0) fl = INF;
                } else {
                    // warp-uniform broadcast poll of slot d
                    unsigned long long pk = lds_vol64(&bnd[w - 1][d & (RING - 1)]);
                    while ((int)(pk >> 32) != d)
                        pk = lds_vol64(&bnd[w - 1][d & (RING - 1)]);
                    if (lane == 0) fl = __uint_as_float((unsigned)pk);
                }
            }
        }
    }

    // ================= TAIL: d in [j0+512, j0+542], generic body =================
    for (int d = j0 + 512; d <= j0 + 542; ++d) {
        float fl = __shfl_up_sync(0xffffffffu, curC, 1);   // lane0 inactive: no consume
        const int  i = d - jme;                            // >= 1
        const bool v = (i < NN);
        float4 q = sq[i & 511];
        float bx = q.x - yj;
        float m  = bx * bx;
        float ut = transf(q.y, bx, q.z, m);
        float lt = transf(al, -bx, al2, m);
        float dd = pdiag + m;
        float du = curC  + ut;
        float cl = fl    + lt;
        float c  = softmin3f(dd, du, cl);
        if (v) {
            pdiag = fl; curC = c;
            if (lane == 31 && w < NW - 1)
                sts_vol64(&bnd[w][d & (RING - 1)],
                          ((unsigned long long)(unsigned)d << 32) |
                          (unsigned long long)__float_as_uint(c));
        }
    }

    // fused mean-reduction: last finishing CTA sums and writes out
    if (t == NT - 1) {
        g_costs[b] = curC;                 // C[511,511]
        __threadfence();
        int old = atomicAdd(&g_ctr, 1);
        if (old == B - 1) {
            __threadfence();
            float s = 0.0f;
            for (int i2 = 0; i2 < B; ++i2)
                s += *((volatile float*)&g_costs[i2]);
            out[0] = s * (1.0f / (float)B);
            atomicExch(&g_ctr, 0);         // reset for next graph replay
        }
    }
}

extern "C" void kernel_launch(void* const* d_in, const int* in_sizes, int n_in,
                              void* d_out, int out_size) {
    const float* x = (const float*)d_in[0];
    const float* y = (const float*)d_in[1];
    int B = in_sizes[0] / NN;   // 64
    if (B > MAXB) B = MAXB;
    soft_msm_kernel<<<B, NT>>>(x, y, (float*)d_out, B);
}

// round 15
// speedup vs baseline: 1.8934x; 1.8934x over previous
#include <cuda_runtime.h>

#define NN 512          // T = U = 512
#define NT 128          // 4 warps, 2 interleaved cols/thread, 256 cols/CTA, 2 CTAs/batch
#define NWP 4
#define RING 256        // intra-CTA ring slots (structural lead ~64)
#define C_CONST 1.0f
#define GEPS 1e-9f
#define MAXB 64

__device__ float g_costs[MAXB];
__device__ int g_ctr = 0;
// inter-CTA boundary ring: one slot per diagonal (no wraparound). (tag<<32)|valbits.
__device__ unsigned long long g_bnd[MAXB][1024];

// ---- fence-free 8B tag|value handoffs (8B accesses are single-copy atomic) ----
__device__ __forceinline__ void sts_vol64(unsigned long long* p, unsigned long long v) {
    unsigned a = (unsigned)__cvta_generic_to_shared(p);
    asm volatile("st.volatile.shared.b64 [%0], %1;" :: "r"(a), "l"(v) : "memory");
}
__device__ __forceinline__ unsigned long long lds_vol64(unsigned long long* p) {
    unsigned a = (unsigned)__cvta_generic_to_shared(p);
    unsigned long long v;
    asm volatile("ld.volatile.shared.b64 %0, [%1];" : "=l"(v) : "r"(a) : "memory");
    return v;
}
__device__ __forceinline__ void stg_vol64(unsigned long long* p, unsigned long long v) {
    asm volatile("st.volatile.global.b64 [%0], %1;" :: "l"(p), "l"(v) : "memory");
}
__device__ __forceinline__ unsigned long long ldg_vol64(const unsigned long long* p) {
    unsigned long long v;
    asm volatile("ld.volatile.global.b64 %0, [%1];" : "=l"(v) : "l"(p) : "memory");
    return v;
}

// ln(1+x) for x in [0,1] on the FMA pipe (no MUFU):
// ln(1+x) = ln(3/2) + ln(1+s), s = (2x-1)/3, |s| <= 1/3; 7-term series, |err| <= 2e-5
__device__ __forceinline__ float log1p_unit(float x) {
    float s = fmaf(x, 0.66666667f, -0.33333333f);
    float p = 0.14285714f;
    p = fmaf(p, s, -0.16666667f);
    p = fmaf(p, s,  0.2f);
    p = fmaf(p, s, -0.25f);
    p = fmaf(p, s,  0.33333333f);
    p = fmaf(p, s, -0.5f);
    p = fmaf(p, s,  1.0f);
    return fmaf(s, p, 0.40546511f);
}

__device__ __forceinline__ float transf(float a, float b, float A, float B) {
    float u = a * b;
    float w = 0.5f * (1.0f + u * rsqrtf(fmaf(u, u, GEPS)));   // 1 - gate
    float mn = fminf(A, B);
    float mx = fmaxf(A, B);
    float sm = mn - log1p_unit(__expf(mn - mx));              // softmin2 (poly log)
    return fmaf(w, sm, C_CONST);
}

// softmin3, min-arm exp folded to 1; INF-safe for boundary arms (MUFU log: on chain)
__device__ __forceinline__ float softmin3f(float a, float b, float c) {
    float mn    = fminf(a, fminf(b, c));
    float mx    = fmaxf(a, fmaxf(b, c));
    float ab_mn = fminf(a, b);
    float ab_mx = fmaxf(a, b);
    float md    = fmaxf(ab_mn, fminf(ab_mx, c));              // median
    float s = 1.0f + __expf(mn - md) + __expf(mn - mx);
    return mn - __logf(s);
}

__global__ __launch_bounds__(NT, 1)
void soft_msm_kernel(const float* __restrict__ x, const float* __restrict__ y,
                     float* __restrict__ out, int B) {
    __shared__ float4 sqp[2][NN / 2];                  // parity-split: sqp[p][k] = row 2k+p
    __shared__ unsigned long long bnd[NWP - 1][RING];  // intra-CTA boundary rings

    const int blk  = blockIdx.x;
    const int b    = blk >> 1;
    const int half = blk & 1;              // 0: cols 0..255, 1: cols 256..511
    const int t    = threadIdx.x;
    const int w    = t >> 5;
    const int lane = t & 31;
    const int jE   = half * 256 + 2 * t;   // my even column
    const int jO   = jE + 1;               // my odd column
    const int base = half * 256 + 64 * w;  // lane0's even column = first diagonal touched

    const float* xb = x + b * NN;
    const float* yb = y + b * NN;

    const float yE   = yb[jE];
    const float yO   = yb[jO];
    const float yEm1 = (jE > 0) ? yb[jE - 1] : 0.0f;
    const float alE  = yE - yEm1;
    const float alO  = yO - yE;
    const float alE2 = alE * alE;
    const float alO2 = alO * alO;

    for (int r = t; r < NN; r += NT) {
        float xv = xb[r];
        float sv = (r > 0) ? (xv - xb[r - 1]) : 0.0f;
        sqp[r & 1][r >> 1] = make_float4(xv, sv, sv * sv, 0.0f);
    }
    for (int i = t; i < (NWP - 1) * RING; i += NT)
        ((unsigned long long*)bnd)[i] = 0xFFFFFFFF00000000ull;
    __syncthreads();

    const float INF = __int_as_float(0x7f800000);
    const bool leftINF = (half == 0) && (w == 0);       // col-0 boundary via INF arm
    const bool gCons   = (half == 1) && (w == 0);       // consumes inter-CTA ring
    const bool gProd   = (half == 0) && (w == NWP - 1); // produces inter-CTA ring

    // carried DP state
    float prevE  = 0.0f;                        // own even col @ d-1
    float prevO  = 0.0f;                        // own odd col  @ d-1
    float prev2E = 0.0f;                        // own even col @ d-2
    float pdiagE = (jE == 0) ? INF : 0.0f;      // left odd col @ d-2
    if (half == 0 && t == 0) { float d0 = xb[0] - yE; prevE = d0 * d0; }   // C[0,0]

    // ================= HEAD: d in [dstart, base+63], generic body =================
    {
        const int dstart = leftINF ? 1 : base;
        for (int d = dstart; d <= base + 63; ++d) {
            float fl = __shfl_up_sync(0xffffffffu, prevO, 1);
            if (lane == 0) {
                if (leftINF) fl = INF;
                else if (gCons) {
                    unsigned long long pk = ldg_vol64(&g_bnd[b][d - 1]);
                    while ((int)(pk >> 32) != d - 1) pk = ldg_vol64(&g_bnd[b][d - 1]);
                    fl = __uint_as_float((unsigned)pk);
                } else {
                    unsigned long long pk = lds_vol64(&bnd[w - 1][(d - 1) & (RING - 1)]);
                    while ((int)(pk >> 32) != d - 1)
                        pk = lds_vol64(&bnd[w - 1][(d - 1) & (RING - 1)]);
                    fl = __uint_as_float((unsigned)pk);
                }
            }
            const int  iE = d - jE;
            const int  iO = iE - 1;
            const bool vE = (iE >= 0);
            const bool vO = (iO >= 0);
            const int  kE = min(max(iE, 0), NN - 1);
            const int  kO = min(max(iO, 0), NN - 1);
            float4 qE = sqp[kE & 1][kE >> 1];
            float4 qO = sqp[kO & 1][kO >> 1];

            float bxE = qE.x - yE, mE = bxE * bxE;
            float utE = transf(qE.y, bxE, qE.z, mE);
            float ltE = transf(alE, -bxE, alE2, mE);
            float dd = pdiagE + mE, du = prevE + utE, cl = fl + ltE;
            if (iE == 0) { dd = INF; du = INF; }
            float cE = softmin3f(dd, du, cl);

            float bxO = qO.x - yO, mO = bxO * bxO;
            float utO = transf(qO.y, bxO, qO.z, mO);
            float ltO = transf(alO, -bxO, alO2, mO);
            float ddo = prev2E + mO, duo = prevO + utO, clo = prevE + ltO;
            if (iO == 0) { ddo = INF; duo = INF; }
            float cO = softmin3f(ddo, duo, clo);

            if (vE) { pdiagE = fl; prev2E = prevE; prevE = cE; }
            if (vO) {
                prevO = cO;
                if (lane == 31) {
                    unsigned long long pk = ((unsigned long long)(unsigned)d << 32) |
                                            (unsigned long long)__float_as_uint(cO);
                    if (w < NWP - 1) sts_vol64(&bnd[w][d & (RING - 1)], pk);
                    else if (gProd)  stg_vol64(&g_bnd[b][d], pk);
                }
            }
        }
    }

    // ============ STEADY: d in [base+64, base+511], lean body, all cells valid ============
    {
        float qval = 0.0f; int qcnt = 0, qpos = 0;     // gCons batched queue

        // preamble: fl for d = base+64 (left odd @ base+63)
        float fl = __shfl_up_sync(0xffffffffu, prevO, 1);
        if (leftINF) {
            if (lane == 0) fl = INF;
        } else if (gCons) {
            const int qb = base + 63;
            unsigned long long pk;
            for (;;) {
                pk = ldg_vol64(&g_bnd[b][qb + lane]);
                unsigned ball = __ballot_sync(0xffffffffu, (int)(pk >> 32) == qb + lane);
                qcnt = (ball == 0xffffffffu) ? 32 : (__ffs(~ball) - 1);
                if (qcnt > 0) break;
            }
            qval = __uint_as_float((unsigned)pk);
            float qv0 = __shfl_sync(0xffffffffu, qval, 0);
            qpos = 1;
            if (lane == 0) fl = qv0;
        } else {
            unsigned long long pk = lds_vol64(&bnd[w - 1][(base + 63) & (RING - 1)]);
            while ((int)(pk >> 32) != base + 63)
                pk = lds_vol64(&bnd[w - 1][(base + 63) & (RING - 1)]);
            if (lane == 0) fl = __uint_as_float((unsigned)pk);
        }

        #pragma unroll 2
        for (int d = base + 64; d <= base + 511; ++d) {
            const int iE = d - jE;                     // 2..511 interior
            const int iO = iE - 1;                     // 1..510 interior
            float4 qE = sqp[d & 1][iE >> 1];           // parity(iE) == parity(d)
            float4 qO = sqp[(d & 1) ^ 1][iO >> 1];

            float bxE = qE.x - yE, mE = bxE * bxE;
            float utE = transf(qE.y, bxE, qE.z, mE);
            float ltE = transf(alE, -bxE, alE2, mE);
            float dd = pdiagE + mE, du = prevE + utE, cl = fl + ltE;
            float cE = softmin3f(dd, du, cl);          // INF arms (col 0) absorbed exactly

            float bxO = qO.x - yO, mO = bxO * bxO;
            float utO = transf(qO.y, bxO, qO.z, mO);
            float ltO = transf(alO, -bxO, alO2, mO);
            float ddo = prev2E + mO, duo = prevO + utO, clo = prevE + ltO;
            float cO = softmin3f(ddo, duo, clo);

            pdiagE = fl; prev2E = prevE; prevE = cE; prevO = cO;

            if (lane == 31) {
                unsigned long long pk = ((unsigned long long)(unsigned)d << 32) |
                                        (unsigned long long)__float_as_uint(cO);
                if (w < NWP - 1) sts_vol64(&bnd[w][d & (RING - 1)], pk);
                else if (gProd)  stg_vol64(&g_bnd[b][d], pk);
            }

            // fromLeft for next iteration (poll-ahead, off the critical chain)
            fl = __shfl_up_sync(0xffffffffu, cO, 1);
            if (d <= base + 510) {
                if (leftINF) {
                    if (lane == 0) fl = INF;
                } else if (gCons) {
                    if (qpos >= qcnt) {
                        unsigned long long pk;
                        for (;;) {
                            pk = ldg_vol64(&g_bnd[b][d + lane]);
                            unsigned ball = __ballot_sync(0xffffffffu,
                                                          (int)(pk >> 32) == d + lane);
                            qcnt = (ball == 0xffffffffu) ? 32 : (__ffs(~ball) - 1);
                            if (qcnt > 0) break;
                        }
                        qval = __uint_as_float((unsigned)pk);
                        qpos = 0;
                    }
                    float qvv = __shfl_sync(0xffffffffu, qval, qpos);
                    qpos++;
                    if (lane == 0) fl = qvv;
                } else {
                    // warp-uniform broadcast poll of slot d
                    unsigned long long pk = lds_vol64(&bnd[w - 1][d & (RING - 1)]);
                    while ((int)(pk >> 32) != d)
                        pk = lds_vol64(&bnd[w - 1][d & (RING - 1)]);
                    if (lane == 0) fl = __uint_as_float((unsigned)pk);
                }
            }
        }
    }

    // ================= TAIL: d in [base+512, base+574], generic body =================
    for (int d = base + 512; d <= base + 574; ++d) {
        float fl = __shfl_up_sync(0xffffffffu, prevO, 1);   // left lane holds its final value
        const int  iE = d - jE;
        const int  iO = iE - 1;
        const bool vE = (iE < NN);
        const bool vO = (iO < NN);
        const int  kE = min(iE, NN - 1);
        const int  kO = min(iO, NN - 1);
        float4 qE = sqp[kE & 1][kE >> 1];
        float4 qO = sqp[kO & 1][kO >> 1];

        float bxE = qE.x - yE, mE = bxE * bxE;
        float utE = transf(qE.y, bxE, qE.z, mE);
        float ltE = transf(alE, -bxE, alE2, mE);
        float cE = softmin3f(pdiagE + mE, prevE + utE, fl + ltE);

        float bxO = qO.x - yO, mO = bxO * bxO;
        float utO = transf(qO.y, bxO, qO.z, mO);
        float ltO = transf(alO, -bxO, alO2, mO);
        float cO = softmin3f(prev2E + mO, prevO + utO, prevE + ltO);

        if (vE) { pdiagE = fl; prev2E = prevE; prevE = cE; }
        if (vO) {
            prevO = cO;
            if (lane == 31) {
                unsigned long long pk = ((unsigned long long)(unsigned)d << 32) |
                                        (unsigned long long)__float_as_uint(cO);
                if (w < NWP - 1) sts_vol64(&bnd[w][d & (RING - 1)], pk);
                else if (gProd)  stg_vol64(&g_bnd[b][d], pk);
            }
        }
    }

    // fused mean-reduction: last finishing half-1 CTA sums and writes out
    if (half == 1 && t == NT - 1) {
        g_costs[b] = prevO;                 // C[511,511]  (jO = 511)
        __threadfence();
        int old = atomicAdd(&g_ctr, 1);
        if (old == B - 1) {
            __threadfence();
            float s = 0.0f;
            for (int i2 = 0; i2 < B; ++i2)
                s += *((volatile float*)&g_costs[i2]);
            out[0] = s * (1.0f / (float)B);
            atomicExch(&g_ctr, 0);          // reset for next graph replay
        }
    }
}

extern "C" void kernel_launch(void* const* d_in, const int* in_sizes, int n_in,
                              void* d_out, int out_size) {
    const float* x = (const float*)d_in[0];
    const float* y = (const float*)d_in[1];
    int B = in_sizes[0] / NN;   // 64
    if (B > MAXB) B = MAXB;
    soft_msm_kernel<<<2 * B, NT>>>(x, y, (float*)d_out, B);
}